// round 13
// baseline (speedup 1.0000x reference)
#include <cuda_runtime.h>
#include <cuda_bf16.h>
#include <string.h>

#define N_NODES 100000
#define C 32
#define E_EDGES 3200000
#define SPMM_WARPS 8
#define SPMM_GRID 1036

// ---- scratch (no allocations allowed; zero at load, and each call re-zeroes before exit) ----
__device__ float         g_deg[N_NODES];        // starts 0 every call (self-loop folded as deg+1)
__device__ float         g_ld[N_NODES];         // fp32 dinv, low 6 mantissa bits = (32|label) if masked else 0
__device__ __nv_bfloat16 g_qh[N_NODES * C];     // q[c][j] = dinv[c] * p[c][j], bf16
__device__ int2          g_cmp[E_EDGES];        // compacted kept edges: {col | label<<17, f32 vw}
__device__ float         g_H[C * C];            // unnormalized class-compat accumulator (0 at call start)
__device__ int           g_mode;                // mask dtype: 0=u8, 1=i32, 2=f32, 3=bf16
__device__ int           g_cnt;                 // kept-edge count (0 at call start)
__device__ int           g_done;                // spmm done-counter (0 at call start)

// ---------------------------------------------------------------- degree (vectorized) + mask sniff (block 0, warp 0)
__global__ void k_deg(const int4* __restrict__ row4, const float4* __restrict__ w4,
                      const unsigned char* __restrict__ m) {
    if (blockIdx.x == 0 && threadIdx.x < 32) {
        int lane = threadIdx.x;
        int nz0 = 0, nz1 = 0, nz2 = 0, nz3 = 0, c01 = 0, c3F = 0;
        for (int base = 0; base < 4096; base += 32) {
            unsigned char b = m[base + lane];        // (base+lane)&3 == lane&3
            unsigned nzm = __ballot_sync(0xFFFFFFFFu, b != 0);
            unsigned m01 = __ballot_sync(0xFFFFFFFFu, b == 0x01);
            unsigned m3F = __ballot_sync(0xFFFFFFFFu, b == 0x3F);
            nz0 += __popc(nzm & 0x11111111u);
            nz1 += __popc(nzm & 0x22222222u);
            nz2 += __popc(nzm & 0x44444444u);
            nz3 += __popc(nzm & 0x88888888u);
            c01 += __popc(m01);
            c3F += __popc(m3F);
        }
        if (lane == 0) {
            int mode;
            if (nz1 == 0 && nz2 == 0 && nz3 == 0)
                mode = 1;                                        // int32 (0/1, LE)
            else if (c01 == 0 && c3F > 0)
                mode = (nz0 == 0 && nz1 == 0) ? 2 : 3;           // float32 : bf16
            else
                mode = 0;                                        // uint8 bool
            g_mode = mode;
        }
    }

    int e = blockIdx.x * blockDim.x + threadIdx.x;
    if (e < E_EDGES / 4) {
        int4   r = row4[e];
        float4 w = w4[e];
        atomicAdd(&g_deg[r.x], w.x);
        atomicAdd(&g_deg[r.y], w.y);
        atomicAdd(&g_deg[r.z], w.z);
        atomicAdd(&g_deg[r.w], w.w);
    }
}

__device__ __forceinline__ bool read_mask(const unsigned char* p, int node, int mode) {
    if (mode == 1) return ((const int*)p)[node] != 0;
    if (mode == 2) return ((const float*)p)[node] != 0.0f;
    if (mode == 3) return ((const unsigned short*)p)[node] != 0;
    return p[node] != 0;
}

// ---------------------------------------------------------------- per-node: softmax / mask / dinv / q / self-loop diag
__global__ __launch_bounds__(256) void k_node(const float* __restrict__ x,
                                              const float* __restrict__ y,
                                              const unsigned char* __restrict__ mask) {
    __shared__ float sdiag[C];
    int tid = threadIdx.x;
    if (tid < C) sdiag[tid] = 0.0f;
    __syncthreads();

    int node = blockIdx.x * 256 + tid;
    if (node < N_NODES) {
        int  mode = g_mode;
        bool msk  = read_mask(mask, node, mode);
        float dinv = rsqrtf(g_deg[node] + 1.0f);  // +1 = self-loop weight
        unsigned packed[16];
        unsigned enc;

        if (msk) {
            // label = argmax of one-hot row (only masked nodes need y)
            const float4* yr = (const float4*)(y + (size_t)node * C);
            int lab = 0;
            #pragma unroll
            for (int i = 0; i < 8; i++) {
                float4 q = yr[i];
                lab = (q.x > 0.5f) ? 4 * i     : lab;
                lab = (q.y > 0.5f) ? 4 * i + 1 : lab;
                lab = (q.z > 0.5f) ? 4 * i + 2 : lab;
                lab = (q.w > 0.5f) ? 4 * i + 3 : lab;
            }
            __nv_bfloat16 h = __float2bfloat16(dinv);
            unsigned hb;
            { unsigned short s; memcpy(&s, &h, 2); hb = s; }
            #pragma unroll
            for (int i = 0; i < 16; i++) {
                unsigned lo = (lab == 2 * i)     ? hb : 0u;
                unsigned hi = (lab == 2 * i + 1) ? hb : 0u;
                packed[i] = lo | (hi << 16);
            }
            atomicAdd(&sdiag[lab], dinv * dinv);             // self-loop diag
            enc = (__float_as_uint(dinv) & ~63u) | 32u | (unsigned)lab;
        } else {
            const float4* xr = (const float4*)(x + (size_t)node * C);
            float v[32];
            #pragma unroll
            for (int i = 0; i < 8; i++) {
                float4 q = xr[i];
                v[4*i] = q.x; v[4*i+1] = q.y; v[4*i+2] = q.z; v[4*i+3] = q.w;
            }
            float m0 = v[0], m1 = v[1], m2 = v[2], m3 = v[3];
            #pragma unroll
            for (int r = 4; r < 32; r += 4) {
                m0 = fmaxf(m0, v[r]); m1 = fmaxf(m1, v[r+1]);
                m2 = fmaxf(m2, v[r+2]); m3 = fmaxf(m3, v[r+3]);
            }
            float mx = fmaxf(fmaxf(m0, m1), fmaxf(m2, m3));
            float a0 = 0.f, a1 = 0.f, a2 = 0.f, a3 = 0.f;
            #pragma unroll
            for (int r = 0; r < 32; r += 4) {
                v[r]   = __expf(v[r]   - mx); a0 += v[r];
                v[r+1] = __expf(v[r+1] - mx); a1 += v[r+1];
                v[r+2] = __expf(v[r+2] - mx); a2 += v[r+2];
                v[r+3] = __expf(v[r+3] - mx); a3 += v[r+3];
            }
            float f = dinv / ((a0 + a1) + (a2 + a3));
            #pragma unroll
            for (int i = 0; i < 16; i++) {
                __nv_bfloat162 hh = __float22bfloat162_rn(make_float2(v[2*i] * f, v[2*i+1] * f));
                memcpy(&packed[i], &hh, 4);
            }
            enc = __float_as_uint(dinv) & ~63u;
        }

        uint4* dst = (uint4*)(g_qh + (size_t)node * C);
        dst[0] = make_uint4(packed[0],  packed[1],  packed[2],  packed[3]);
        dst[1] = make_uint4(packed[4],  packed[5],  packed[6],  packed[7]);
        dst[2] = make_uint4(packed[8],  packed[9],  packed[10], packed[11]);
        dst[3] = make_uint4(packed[12], packed[13], packed[14], packed[15]);
        g_ld[node] = __uint_as_float(enc);
    }
    __syncthreads();
    if (tid < C && sdiag[tid] != 0.0f) atomicAdd(&g_H[tid * C + tid], sdiag[tid]);
}

// ---------------------------------------------------------------- compaction: 8 edges/thread, all loads front-batched
// Also re-zeroes g_deg for the NEXT call (k_node already consumed it).
__global__ __launch_bounds__(256) void k_compact(const int4* __restrict__ row4,
                                                 const int4* __restrict__ col4,
                                                 const float4* __restrict__ w4) {
    int i = blockIdx.x * blockDim.x + threadIdx.x;       // chunk of 8 edges
    int lane = threadIdx.x & 31;

    if (i < N_NODES) g_deg[i] = 0.0f;                    // cleanup for next call
    if (i >= E_EDGES / 8) return;

    // front-batched streaming loads (rows, cols, weights together)
    int4   ra = row4[2 * i];
    int4   rb = row4[2 * i + 1];
    int4   ca = col4[2 * i];
    int4   cb = col4[2 * i + 1];
    float4 wa = w4[2 * i];
    float4 wb = w4[2 * i + 1];
    int rr[8] = {ra.x, ra.y, ra.z, ra.w, rb.x, rb.y, rb.z, rb.w};

    // front-batched MLP=8 gathers
    float d[8];
    #pragma unroll
    for (int k = 0; k < 8; k++) d[k] = g_ld[rr[k]];

    unsigned t[8];
    bool kp[8];
    int cnt = 0;
    #pragma unroll
    for (int k = 0; k < 8; k++) {
        t[k]  = __float_as_uint(d[k]) & 63u;
        kp[k] = t[k] >= 32u;
        cnt  += (int)kp[k];
    }

    // inclusive warp scan
    int ofs = cnt;
    #pragma unroll
    for (int dd = 1; dd < 32; dd <<= 1) {
        int n = __shfl_up_sync(0xFFFFFFFFu, ofs, dd);
        if (lane >= dd) ofs += n;
    }
    int total = __shfl_sync(0xFFFFFFFFu, ofs, 31);
    int basep = 0;
    if (lane == 31 && total) basep = atomicAdd(&g_cnt, total);
    basep = __shfl_sync(0xFFFFFFFFu, basep, 31);
    int p = basep + ofs - cnt;

    int   cc[8] = {ca.x, ca.y, ca.z, ca.w, cb.x, cb.y, cb.z, cb.w};
    float ww[8] = {wa.x, wa.y, wa.z, wa.w, wb.x, wb.y, wb.z, wb.w};
    #pragma unroll
    for (int k = 0; k < 8; k++)
        if (kp[k])
            g_cmp[p++] = make_int2(cc[k] | (int)((t[k] - 32u) << 17),
                                   __float_as_int(d[k] * ww[k]));
}

// ---------------------------------------------------------------- dense sweep -> 32x32 tile, + last-block Sinkhorn tail
__global__ __launch_bounds__(256) void k_spmm(float* __restrict__ out) {
    __shared__ float Hs[SPMM_WARPS][C * C];
    __shared__ int s_last;
    int lane = threadIdx.x & 31;
    int wid  = threadIdx.x >> 5;
    float* Hw = Hs[wid];
    for (int i = lane; i < C * C; i += 32) Hw[i] = 0.0f;
    __syncwarp();

    const unsigned short* qh = (const unsigned short*)g_qh;
    int total = g_cnt;
    int gw = blockIdx.x * SPMM_WARPS + wid;
    int nw = gridDim.x * SPMM_WARPS;

    for (int base = gw * 32; base < total; base += nw * 32) {
        int e = base + lane;
        int2 ent = (e < total) ? g_cmp[e] : make_int2(0, 0);
        if (base + 32 <= total) {
            #pragma unroll
            for (int g = 0; g < 4; g++) {
                int pk[8]; float vv[8]; unsigned qr[8];
                #pragma unroll
                for (int k = 0; k < 8; k++) {
                    pk[k] = __shfl_sync(0xFFFFFFFFu, ent.x, g * 8 + k);
                    vv[k] = __uint_as_float(__shfl_sync(0xFFFFFFFFu, ent.y, g * 8 + k));
                }
                #pragma unroll
                for (int k = 0; k < 8; k++)
                    qr[k] = qh[(pk[k] & 0x1FFFF) * C + lane];     // MLP=8 gather burst
                #pragma unroll
                for (int k = 0; k < 8; k++) {
                    float qf = __uint_as_float(qr[k] << 16);       // bf16 -> f32 via shift
                    Hw[(pk[k] >> 17) * C + lane] += vv[k] * qf;
                }
            }
        } else {
            int cnt = total - base;
            for (int k = 0; k < cnt; k++) {
                int   pk = __shfl_sync(0xFFFFFFFFu, ent.x, k);
                float v  = __uint_as_float(__shfl_sync(0xFFFFFFFFu, ent.y, k));
                float qf = __uint_as_float((unsigned)qh[(pk & 0x1FFFF) * C + lane] << 16);
                Hw[(pk >> 17) * C + lane] += v * qf;
            }
        }
    }

    __syncthreads();
    for (int i = threadIdx.x; i < C * C; i += blockDim.x) {
        float s = 0.0f;
        #pragma unroll
        for (int wg = 0; wg < SPMM_WARPS; wg++) s += Hs[wg][i];
        atomicAdd(&g_H[i], s);
    }

    // ---- last-block tail: Sinkhorn + cleanup ----
    __threadfence();                                   // publish this block's H atomics
    __syncthreads();
    if (threadIdx.x == 0)
        s_last = (atomicAdd(&g_done, 1) == (int)gridDim.x - 1);
    __syncthreads();
    if (!s_last) return;
    __threadfence();                                   // acquire all blocks' H atomics

    if (threadIdx.x < 32) {
        int t = threadIdx.x;
        float v[C], u[C];
        #pragma unroll
        for (int r = 0; r < C; r++) v[r] = __ldcg(&g_H[r * C + t]);   // column t
        #pragma unroll
        for (int j = 0; j < C; j++) u[j] = __ldcg(&g_H[t * C + j]);   // row t

        // cleanup for next call
        #pragma unroll
        for (int r = 0; r < C; r++) g_H[r * C + t] = 0.0f;
        if (t == 0) { g_cnt = 0; g_done = 0; }

        float cs = 1.0f, rs = 1.0f;
        for (int it = 0; it < 3000; it++) {
            float s0 = 0.f, s1 = 0.f, s2 = 0.f, s3 = 0.f;
            #pragma unroll
            for (int i = 0; i < C; i += 4) {
                s0 += __shfl_sync(0xFFFFFFFFu, rs, i)     * v[i];
                s1 += __shfl_sync(0xFFFFFFFFu, rs, i + 1) * v[i + 1];
                s2 += __shfl_sync(0xFFFFFFFFu, rs, i + 2) * v[i + 2];
                s3 += __shfl_sync(0xFFFFFFFFu, rs, i + 3) * v[i + 3];
            }
            float S = (s0 + s1) + (s2 + s3);
            float c_new = 1.0f / S;

            float q0 = 0.f, q1 = 0.f, q2 = 0.f, q3 = 0.f;
            #pragma unroll
            for (int j = 0; j < C; j += 4) {
                q0 += __shfl_sync(0xFFFFFFFFu, c_new, j)     * u[j];
                q1 += __shfl_sync(0xFFFFFFFFu, c_new, j + 1) * u[j + 1];
                q2 += __shfl_sync(0xFFFFFFFFu, c_new, j + 2) * u[j + 2];
                q3 += __shfl_sync(0xFFFFFFFFu, c_new, j + 3) * u[j + 3];
            }
            float S2 = (q0 + q1) + (q2 + q3);
            float r_new = 1.0f / S2;

            float devc = cs * S  - 1.0f;
            float devr = rs * S2 - 1.0f;
            cs = c_new;
            rs = r_new;
            if (it & 1) {
                float dev = fmaxf(fabsf(devc), fabsf(devr));
                if (it >= 5 && __all_sync(0xFFFFFFFFu, dev < 1e-4f)) break;
            }
        }

        // out[i][t] = r_i * H0[i][t] * c_t
        #pragma unroll
        for (int r = 0; r < C; r++)
            out[r * C + t] = __shfl_sync(0xFFFFFFFFu, rs, r) * v[r] * cs;
    }
}

// ---------------------------------------------------------------- launch
extern "C" void kernel_launch(void* const* d_in, const int* in_sizes, int n_in,
                              void* d_out, int out_size) {
    const int*           ei   = (const int*)d_in[0];      // (2, E): rows then cols
    const float*         ew   = (const float*)d_in[1];    // (E,)
    const float*         x    = (const float*)d_in[2];    // (N, C)
    const float*         y    = (const float*)d_in[3];    // (N, C) one-hot
    const unsigned char* mask = (const unsigned char*)d_in[4];  // (N,) dtype sniffed

    const int* row = ei;
    const int* col = ei + E_EDGES;

    k_deg<<<(E_EDGES / 4 + 255) / 256, 256>>>((const int4*)row, (const float4*)ew, mask);
    k_node<<<(N_NODES + 255) / 256, 256>>>(x, y, mask);
    k_compact<<<(E_EDGES / 8 + 255) / 256, 256>>>((const int4*)row, (const int4*)col, (const float4*)ew);
    k_spmm<<<SPMM_GRID, 256>>>((float*)d_out);
}

// round 14
// speedup vs baseline: 1.1265x; 1.1265x over previous
#include <cuda_runtime.h>
#include <cuda_bf16.h>
#include <string.h>

#define N_NODES 100000
#define C 32
#define E_EDGES 3200000
#define SPMM_WARPS 8
#define SPMM_GRID 1036

// ---- scratch (no allocations allowed; zero at load, each call re-zeroes before exit) ----
__device__ float         g_deg[N_NODES];        // starts 0 every call (self-loop folded as deg+1)
__device__ float         g_ld[N_NODES];         // fp32 dinv, low 6 mantissa bits = (32|label) if masked else 0
__device__ __nv_bfloat16 g_qh[N_NODES * C];     // q[c][j] = dinv[c] * p[c][j], bf16
__device__ int2          g_cmp[E_EDGES];        // compacted kept edges: {col | label<<17, f32 vw}
__device__ float         g_H[C * C];            // unnormalized class-compat accumulator (0 at call start)
__device__ int           g_mode;                // mask dtype: 0=u8, 1=i32, 2=f32, 3=bf16
__device__ int           g_cnt;                 // kept-edge count (0 at call start)

// ---------------------------------------------------------------- degree (vectorized) + mask sniff (block 0, warp 0)
__global__ void k_deg(const int4* __restrict__ row4, const float4* __restrict__ w4,
                      const unsigned char* __restrict__ m) {
    if (blockIdx.x == 0 && threadIdx.x < 32) {
        int lane = threadIdx.x;
        int nz0 = 0, nz1 = 0, nz2 = 0, nz3 = 0, c01 = 0, c3F = 0;
        for (int base = 0; base < 4096; base += 32) {
            unsigned char b = m[base + lane];        // (base+lane)&3 == lane&3
            unsigned nzm = __ballot_sync(0xFFFFFFFFu, b != 0);
            unsigned m01 = __ballot_sync(0xFFFFFFFFu, b == 0x01);
            unsigned m3F = __ballot_sync(0xFFFFFFFFu, b == 0x3F);
            nz0 += __popc(nzm & 0x11111111u);
            nz1 += __popc(nzm & 0x22222222u);
            nz2 += __popc(nzm & 0x44444444u);
            nz3 += __popc(nzm & 0x88888888u);
            c01 += __popc(m01);
            c3F += __popc(m3F);
        }
        if (lane == 0) {
            int mode;
            if (nz1 == 0 && nz2 == 0 && nz3 == 0)
                mode = 1;                                        // int32 (0/1, LE)
            else if (c01 == 0 && c3F > 0)
                mode = (nz0 == 0 && nz1 == 0) ? 2 : 3;           // float32 : bf16
            else
                mode = 0;                                        // uint8 bool
            g_mode = mode;
        }
    }

    int e = blockIdx.x * blockDim.x + threadIdx.x;
    if (e < E_EDGES / 4) {
        int4   r = row4[e];
        float4 w = w4[e];
        atomicAdd(&g_deg[r.x], w.x);
        atomicAdd(&g_deg[r.y], w.y);
        atomicAdd(&g_deg[r.z], w.z);
        atomicAdd(&g_deg[r.w], w.w);
    }
}

__device__ __forceinline__ bool read_mask(const unsigned char* p, int node, int mode) {
    if (mode == 1) return ((const int*)p)[node] != 0;
    if (mode == 2) return ((const float*)p)[node] != 0.0f;
    if (mode == 3) return ((const unsigned short*)p)[node] != 0;
    return p[node] != 0;
}

// ---------------------------------------------------------------- per-node: softmax / mask / dinv / q / self-loop diag
__global__ __launch_bounds__(256) void k_node(const float* __restrict__ x,
                                              const float* __restrict__ y,
                                              const unsigned char* __restrict__ mask) {
    __shared__ float sdiag[C];
    int tid = threadIdx.x;
    if (tid < C) sdiag[tid] = 0.0f;
    __syncthreads();

    int node = blockIdx.x * 256 + tid;
    if (node < N_NODES) {
        int  mode = g_mode;
        bool msk  = read_mask(mask, node, mode);
        float dinv = rsqrtf(g_deg[node] + 1.0f);  // +1 = self-loop weight
        unsigned packed[16];
        unsigned enc;

        if (msk) {
            // label = argmax of one-hot row (only masked nodes need y)
            const float4* yr = (const float4*)(y + (size_t)node * C);
            int lab = 0;
            #pragma unroll
            for (int i = 0; i < 8; i++) {
                float4 q = yr[i];
                lab = (q.x > 0.5f) ? 4 * i     : lab;
                lab = (q.y > 0.5f) ? 4 * i + 1 : lab;
                lab = (q.z > 0.5f) ? 4 * i + 2 : lab;
                lab = (q.w > 0.5f) ? 4 * i + 3 : lab;
            }
            __nv_bfloat16 h = __float2bfloat16(dinv);
            unsigned hb;
            { unsigned short s; memcpy(&s, &h, 2); hb = s; }
            #pragma unroll
            for (int i = 0; i < 16; i++) {
                unsigned lo = (lab == 2 * i)     ? hb : 0u;
                unsigned hi = (lab == 2 * i + 1) ? hb : 0u;
                packed[i] = lo | (hi << 16);
            }
            atomicAdd(&sdiag[lab], dinv * dinv);             // self-loop diag
            enc = (__float_as_uint(dinv) & ~63u) | 32u | (unsigned)lab;
        } else {
            const float4* xr = (const float4*)(x + (size_t)node * C);
            float v[32];
            #pragma unroll
            for (int i = 0; i < 8; i++) {
                float4 q = xr[i];
                v[4*i] = q.x; v[4*i+1] = q.y; v[4*i+2] = q.z; v[4*i+3] = q.w;
            }
            float m0 = v[0], m1 = v[1], m2 = v[2], m3 = v[3];
            #pragma unroll
            for (int r = 4; r < 32; r += 4) {
                m0 = fmaxf(m0, v[r]); m1 = fmaxf(m1, v[r+1]);
                m2 = fmaxf(m2, v[r+2]); m3 = fmaxf(m3, v[r+3]);
            }
            float mx = fmaxf(fmaxf(m0, m1), fmaxf(m2, m3));
            float a0 = 0.f, a1 = 0.f, a2 = 0.f, a3 = 0.f;
            #pragma unroll
            for (int r = 0; r < 32; r += 4) {
                v[r]   = __expf(v[r]   - mx); a0 += v[r];
                v[r+1] = __expf(v[r+1] - mx); a1 += v[r+1];
                v[r+2] = __expf(v[r+2] - mx); a2 += v[r+2];
                v[r+3] = __expf(v[r+3] - mx); a3 += v[r+3];
            }
            float f = dinv / ((a0 + a1) + (a2 + a3));
            #pragma unroll
            for (int i = 0; i < 16; i++) {
                __nv_bfloat162 hh = __float22bfloat162_rn(make_float2(v[2*i] * f, v[2*i+1] * f));
                memcpy(&packed[i], &hh, 4);
            }
            enc = __float_as_uint(dinv) & ~63u;
        }

        uint4* dst = (uint4*)(g_qh + (size_t)node * C);
        dst[0] = make_uint4(packed[0],  packed[1],  packed[2],  packed[3]);
        dst[1] = make_uint4(packed[4],  packed[5],  packed[6],  packed[7]);
        dst[2] = make_uint4(packed[8],  packed[9],  packed[10], packed[11]);
        dst[3] = make_uint4(packed[12], packed[13], packed[14], packed[15]);
        g_ld[node] = __uint_as_float(enc);
    }
    __syncthreads();
    if (tid < C && sdiag[tid] != 0.0f) atomicAdd(&g_H[tid * C + tid], sdiag[tid]);
}

// ---------------------------------------------------------------- compaction: 8 edges/thread, all loads front-batched
// Also re-zeroes g_deg for the NEXT call (k_node already consumed it).
__global__ __launch_bounds__(256) void k_compact(const int4* __restrict__ row4,
                                                 const int4* __restrict__ col4,
                                                 const float4* __restrict__ w4) {
    int i = blockIdx.x * blockDim.x + threadIdx.x;       // chunk of 8 edges
    int lane = threadIdx.x & 31;

    if (i < N_NODES) g_deg[i] = 0.0f;                    // cleanup for next call
    if (i >= E_EDGES / 8) return;

    // front-batched streaming loads (rows, cols, weights together)
    int4   ra = row4[2 * i];
    int4   rb = row4[2 * i + 1];
    int4   ca = col4[2 * i];
    int4   cb = col4[2 * i + 1];
    float4 wa = w4[2 * i];
    float4 wb = w4[2 * i + 1];
    int rr[8] = {ra.x, ra.y, ra.z, ra.w, rb.x, rb.y, rb.z, rb.w};

    // front-batched MLP=8 gathers
    float d[8];
    #pragma unroll
    for (int k = 0; k < 8; k++) d[k] = g_ld[rr[k]];

    unsigned t[8];
    bool kp[8];
    int cnt = 0;
    #pragma unroll
    for (int k = 0; k < 8; k++) {
        t[k]  = __float_as_uint(d[k]) & 63u;
        kp[k] = t[k] >= 32u;
        cnt  += (int)kp[k];
    }

    // inclusive warp scan
    int ofs = cnt;
    #pragma unroll
    for (int dd = 1; dd < 32; dd <<= 1) {
        int n = __shfl_up_sync(0xFFFFFFFFu, ofs, dd);
        if (lane >= dd) ofs += n;
    }
    int total = __shfl_sync(0xFFFFFFFFu, ofs, 31);
    int basep = 0;
    if (lane == 31 && total) basep = atomicAdd(&g_cnt, total);
    basep = __shfl_sync(0xFFFFFFFFu, basep, 31);
    int p = basep + ofs - cnt;

    int   cc[8] = {ca.x, ca.y, ca.z, ca.w, cb.x, cb.y, cb.z, cb.w};
    float ww[8] = {wa.x, wa.y, wa.z, wa.w, wb.x, wb.y, wb.z, wb.w};
    #pragma unroll
    for (int k = 0; k < 8; k++)
        if (kp[k])
            g_cmp[p++] = make_int2(cc[k] | (int)((t[k] - 32u) << 17),
                                   __float_as_int(d[k] * ww[k]));
}

// ---------------------------------------------------------------- dense sweep -> 32x32 tile (lean: no tail, ~40 regs)
__global__ __launch_bounds__(256) void k_spmm() {
    __shared__ float Hs[SPMM_WARPS][C * C];
    int lane = threadIdx.x & 31;
    int wid  = threadIdx.x >> 5;
    float* Hw = Hs[wid];
    for (int i = lane; i < C * C; i += 32) Hw[i] = 0.0f;
    __syncwarp();

    const unsigned short* qh = (const unsigned short*)g_qh;
    int total = g_cnt;
    int gw = blockIdx.x * SPMM_WARPS + wid;
    int nw = gridDim.x * SPMM_WARPS;

    for (int base = gw * 32; base < total; base += nw * 32) {
        int e = base + lane;
        int2 ent = (e < total) ? g_cmp[e] : make_int2(0, 0);
        if (base + 32 <= total) {
            #pragma unroll
            for (int g = 0; g < 4; g++) {
                int pk[8]; float vv[8]; unsigned qr[8];
                #pragma unroll
                for (int k = 0; k < 8; k++) {
                    pk[k] = __shfl_sync(0xFFFFFFFFu, ent.x, g * 8 + k);
                    vv[k] = __uint_as_float(__shfl_sync(0xFFFFFFFFu, ent.y, g * 8 + k));
                }
                #pragma unroll
                for (int k = 0; k < 8; k++)
                    qr[k] = qh[(pk[k] & 0x1FFFF) * C + lane];     // MLP=8 gather burst
                #pragma unroll
                for (int k = 0; k < 8; k++) {
                    float qf = __uint_as_float(qr[k] << 16);       // bf16 -> f32 via shift
                    Hw[(pk[k] >> 17) * C + lane] += vv[k] * qf;
                }
            }
        } else {
            int cnt = total - base;
            for (int k = 0; k < cnt; k++) {
                int   pk = __shfl_sync(0xFFFFFFFFu, ent.x, k);
                float v  = __uint_as_float(__shfl_sync(0xFFFFFFFFu, ent.y, k));
                float qf = __uint_as_float((unsigned)qh[(pk & 0x1FFFF) * C + lane] << 16);
                Hw[(pk >> 17) * C + lane] += v * qf;
            }
        }
    }

    __syncthreads();
    for (int i = threadIdx.x; i < C * C; i += blockDim.x) {
        float s = 0.0f;
        #pragma unroll
        for (int wg = 0; wg < SPMM_WARPS; wg++) s += Hs[wg][i];
        atomicAdd(&g_H[i], s);
    }
}

// ---------------------------------------------------------------- Sinkhorn in scale space + scratch cleanup
__global__ void k_sinkhorn(float* __restrict__ out) {
    int t = threadIdx.x;

    float v[C];   // column t of H0
    float u[C];   // row t of H0
    #pragma unroll
    for (int r = 0; r < C; r++) v[r] = g_H[r * C + t];
    #pragma unroll
    for (int j = 0; j < C; j++) u[j] = g_H[t * C + j];

    // cleanup for next call
    #pragma unroll
    for (int r = 0; r < C; r++) g_H[r * C + t] = 0.0f;
    if (t == 0) g_cnt = 0;

    float cs = 1.0f, rs = 1.0f;
    for (int it = 0; it < 3000; it++) {
        float s0 = 0.f, s1 = 0.f, s2 = 0.f, s3 = 0.f;
        #pragma unroll
        for (int i = 0; i < C; i += 4) {
            s0 += __shfl_sync(0xFFFFFFFFu, rs, i)     * v[i];
            s1 += __shfl_sync(0xFFFFFFFFu, rs, i + 1) * v[i + 1];
            s2 += __shfl_sync(0xFFFFFFFFu, rs, i + 2) * v[i + 2];
            s3 += __shfl_sync(0xFFFFFFFFu, rs, i + 3) * v[i + 3];
        }
        float S = (s0 + s1) + (s2 + s3);
        float c_new = 1.0f / S;

        float q0 = 0.f, q1 = 0.f, q2 = 0.f, q3 = 0.f;
        #pragma unroll
        for (int j = 0; j < C; j += 4) {
            q0 += __shfl_sync(0xFFFFFFFFu, c_new, j)     * u[j];
            q1 += __shfl_sync(0xFFFFFFFFu, c_new, j + 1) * u[j + 1];
            q2 += __shfl_sync(0xFFFFFFFFu, c_new, j + 2) * u[j + 2];
            q3 += __shfl_sync(0xFFFFFFFFu, c_new, j + 3) * u[j + 3];
        }
        float S2 = (q0 + q1) + (q2 + q3);
        float r_new = 1.0f / S2;

        float devc = cs * S  - 1.0f;
        float devr = rs * S2 - 1.0f;
        cs = c_new;
        rs = r_new;
        if (it & 1) {
            float dev = fmaxf(fabsf(devc), fabsf(devr));
            if (it >= 5 && __all_sync(0xFFFFFFFFu, dev < 1e-4f)) break;
        }
    }

    // out[i][t] = r_i * H0[i][t] * c_t
    #pragma unroll
    for (int r = 0; r < C; r++)
        out[r * C + t] = __shfl_sync(0xFFFFFFFFu, rs, r) * v[r] * cs;
}

// ---------------------------------------------------------------- launch
extern "C" void kernel_launch(void* const* d_in, const int* in_sizes, int n_in,
                              void* d_out, int out_size) {
    const int*           ei   = (const int*)d_in[0];      // (2, E): rows then cols
    const float*         ew   = (const float*)d_in[1];    // (E,)
    const float*         x    = (const float*)d_in[2];    // (N, C)
    const float*         y    = (const float*)d_in[3];    // (N, C) one-hot
    const unsigned char* mask = (const unsigned char*)d_in[4];  // (N,) dtype sniffed

    const int* row = ei;
    const int* col = ei + E_EDGES;

    k_deg<<<(E_EDGES / 4 + 255) / 256, 256>>>((const int4*)row, (const float4*)ew, mask);
    k_node<<<(N_NODES + 255) / 256, 256>>>(x, y, mask);
    k_compact<<<(E_EDGES / 8 + 255) / 256, 256>>>((const int4*)row, (const int4*)col, (const float4*)ew);
    k_spmm<<<SPMM_GRID, 256>>>();
    k_sinkhorn<<<1, 32>>>((float*)d_out);
}